// round 9
// baseline (speedup 1.0000x reference)
#include <cuda_runtime.h>
#include <math.h>
#include <stdint.h>
#include <stddef.h>

// Problem constants
#define Bc 32
#define Tc 64
#define Sc 64
#define Vc 32000
#define Ec 512
#define Hc 512
#define KC 1536   // concat width = 2H + E

// Output layout offsets (floats): outputs (B,T,V), h (2,B,H), c (2,B,H), attn (B,T,S)
#define OFF_H   ((size_t)Bc * Tc * Vc)
#define OFF_C   (OFF_H + (size_t)2 * Bc * Hc)
#define OFF_ATT (OFF_C + (size_t)2 * Bc * Hc)

// ---------------- device scratch (no allocations allowed) ----------------
__device__ float g_concat[(size_t)Tc * Bc * KC];   // [t][b][ h1 | ctx | emb ]  12.6 MB
__device__ float g_part[12 * 2048 * Bc];           // split-K partial gates      3 MB
__device__ float g_h[2][2][Bc * Hc];               // [layer][pingpong][b*H+h]
__device__ float g_c[2][Bc * Hc];                  // [layer][b*H+h]
__device__ int   g_cnt[16];                        // last-block counters (self-resetting)

// ---------------- init: copy h0/c0 into state buffers ----------------
__global__ void k_init(const float* __restrict__ h0, const float* __restrict__ c0) {
    int i = blockIdx.x * blockDim.x + threadIdx.x;
    if (i < Bc * Hc) {
        g_h[0][0][i] = h0[i];
        g_h[1][0][i] = h0[Bc * Hc + i];
        g_c[0][i] = c0[i];
        g_c[1][i] = c0[Bc * Hc + i];
    }
}

// ---------------- embedding gather into concat buffer ----------------
__global__ void k_embed(const int* __restrict__ tok, const float* __restrict__ emb) {
    int r = blockIdx.x;          // r = t*32 + b
    int t = r >> 5, b = r & 31;
    int tk = tok[b * Tc + t];
    const float4* src = (const float4*)(emb + (size_t)tk * Ec);
    float4* dst = (float4*)(g_concat + (size_t)r * KC + 2 * Hc);
    for (int i = threadIdx.x; i < Ec / 4; i += blockDim.x) dst[i] = src[i];
}

// ---------------- attention for step t (reads h1 prev, writes ctx + attn) ----------------
__global__ __launch_bounds__(256) void k_attn(const float* __restrict__ enc, int t, int pr,
                                              float* __restrict__ out) {
    int b = blockIdx.x;
    int tid = threadIdx.x, w = tid >> 5, lane = tid & 31;
    const float* q = &g_h[1][pr][b * Hc];
    const float* encb = enc + (size_t)b * Sc * Hc;
    __shared__ float sc[Sc];
    __shared__ float sa[Sc];

    // scores: 8 warps x 8 s each, dot length 512
    #pragma unroll
    for (int i = 0; i < 8; i++) {
        int s = w * 8 + i;
        const float* e = encb + (size_t)s * Hc;
        float acc = 0.f;
        for (int h = lane; h < Hc; h += 32) acc += q[h] * e[h];
        #pragma unroll
        for (int o = 16; o; o >>= 1) acc += __shfl_down_sync(0xffffffffu, acc, o);
        if (lane == 0) sc[s] = acc * 0.04419417382415922f;   // 1/sqrt(512)
    }
    __syncthreads();

    // softmax over 64 (warp 0)
    if (w == 0) {
        float v0 = sc[lane], v1 = sc[lane + 32];
        float m = fmaxf(v0, v1);
        #pragma unroll
        for (int o = 16; o; o >>= 1) m = fmaxf(m, __shfl_xor_sync(0xffffffffu, m, o));
        float e0 = expf(v0 - m), e1 = expf(v1 - m);
        float ssum = e0 + e1;
        #pragma unroll
        for (int o = 16; o; o >>= 1) ssum += __shfl_xor_sync(0xffffffffu, ssum, o);
        float inv = 1.f / ssum;
        sa[lane] = e0 * inv;
        sa[lane + 32] = e1 * inv;
    }
    __syncthreads();

    // write attn weights to output
    if (tid < Sc) out[OFF_ATT + (size_t)b * Tc * Sc + (size_t)t * Sc + tid] = sa[tid];

    // ctx[h] = sum_s a[s]*enc[b][s][h]  -> concat ctx section
    float* crow = g_concat + ((size_t)(t * Bc + b) * KC + Hc);
    for (int h = tid; h < Hc; h += 256) {
        float acc = 0.f;
        #pragma unroll 8
        for (int s = 0; s < Sc; s++) acc += sa[s] * encb[(size_t)s * Hc + h];
        crow[h] = acc;
    }
}

// ---------------- fused LSTM layer: split-K GEMM + last-block gate update ----------------
// grid: (16 hidden-chunks, nseg K-segments of 128).  gates j = g*512 + chunk*32 + u.
__global__ __launch_bounds__(256) void k_lstm(const float* __restrict__ Wih,
                                              const float* __restrict__ Whh,
                                              const float* __restrict__ bih,
                                              const float* __restrict__ bhh,
                                              int layer, int t, int pr, int nx, int nseg) {
    int chunk = blockIdx.x, seg = blockIdx.y;
    int k0 = seg * 128;
    int tid = threadIdx.x, w = tid >> 5, lane = tid & 31;

    // ---- resolve x-segment and W-segment sources (segments never cross 512 boundaries)
    const float* xbase; int xstride;
    const float* wbase; int wstride;
    if (layer == 0) {
        // x = [emb(0:512) | ctx(512:1024) | h0_prev(1024:1536)]
        if (k0 < 2 * Hc) {
            xbase = g_concat + (size_t)(t * Bc) * KC + (k0 < Hc ? 2 * Hc + k0 : k0);
            xstride = KC;
        } else {
            xbase = g_h[0][pr] + (k0 - 2 * Hc);
            xstride = Hc;
        }
        if (k0 < 2 * Hc) { wbase = Wih + k0; wstride = Ec + Hc; }
        else             { wbase = Whh + (k0 - 2 * Hc); wstride = Hc; }
    } else {
        // x = [h0_new(0:512) | h1_prev(512:1024)]
        if (k0 < Hc) { xbase = g_h[0][nx] + k0; xstride = Hc; }
        else         { xbase = g_h[1][pr] + (k0 - Hc); xstride = Hc; }
        if (k0 < Hc) { wbase = Wih + k0; wstride = Hc; }
        else         { wbase = Whh + (k0 - Hc); wstride = Hc; }
    }

    __shared__ float xs[128][33];     // x tile transposed: [k][b]
    __shared__ float wsT[32][129];    // W sub-tile transposed: [k][j_local 0..127] (+1 pad)
    __shared__ int slast;

    // load x tile (32 b x 128 k), coalesced along k, conflict-free smem writes
    #pragma unroll
    for (int ib = 0; ib < 4; ib++) {
        int b = w * 4 + ib;
        const float* xr = xbase + (size_t)b * xstride;
        #pragma unroll
        for (int i = 0; i < 4; i++) {
            int k = lane + 32 * i;
            xs[k][b] = xr[k];
        }
    }

    float acc[4][4] = {};
    int bq = tid & 7;     // b = 4*bq + bi
    int jq = tid >> 3;    // j_local = 4*jq + ji

    for (int kt = 0; kt < 4; kt++) {
        __syncthreads();
        // load W sub-tile: 128 j x 32 k
        #pragma unroll
        for (int i = 0; i < 16; i++) {
            int jl = w * 16 + i;
            int j = ((jl >> 5) << 9) + (chunk << 5) + (jl & 31);
            wsT[lane][jl] = wbase[(size_t)j * wstride + kt * 32 + lane];
        }
        __syncthreads();
        #pragma unroll
        for (int kk = 0; kk < 32; kk++) {
            int kg = kt * 32 + kk;
            float xv0 = xs[kg][4 * bq + 0], xv1 = xs[kg][4 * bq + 1];
            float xv2 = xs[kg][4 * bq + 2], xv3 = xs[kg][4 * bq + 3];
            float wv0 = wsT[kk][4 * jq + 0], wv1 = wsT[kk][4 * jq + 1];
            float wv2 = wsT[kk][4 * jq + 2], wv3 = wsT[kk][4 * jq + 3];
            acc[0][0] += wv0 * xv0; acc[0][1] += wv0 * xv1; acc[0][2] += wv0 * xv2; acc[0][3] += wv0 * xv3;
            acc[1][0] += wv1 * xv0; acc[1][1] += wv1 * xv1; acc[1][2] += wv1 * xv2; acc[1][3] += wv1 * xv3;
            acc[2][0] += wv2 * xv0; acc[2][1] += wv2 * xv1; acc[2][2] += wv2 * xv2; acc[2][3] += wv2 * xv3;
            acc[3][0] += wv3 * xv0; acc[3][1] += wv3 * xv1; acc[3][2] += wv3 * xv2; acc[3][3] += wv3 * xv3;
        }
    }

    // write partials: g_part[seg][j][b]
    #pragma unroll
    for (int ji = 0; ji < 4; ji++) {
        int jl = 4 * jq + ji;
        int j = ((jl >> 5) << 9) + (chunk << 5) + (jl & 31);
        float4 v = make_float4(acc[ji][0], acc[ji][1], acc[ji][2], acc[ji][3]);
        *(float4*)&g_part[((size_t)seg * 2048 + j) * Bc + 4 * bq] = v;
    }
    __threadfence();
    __syncthreads();
    if (tid == 0) {
        int old = atomicAdd(&g_cnt[chunk], 1);
        slast = (old == nseg - 1) ? 1 : 0;
    }
    __syncthreads();
    if (!slast) return;
    __threadfence();   // acquire: order partials reads after the arrival atomic

    // last block for this hidden-chunk: reduce segments, apply gates, update state
    for (int p = tid; p < 1024; p += 256) {
        int u = p >> 5;
        int b = p & 31;
        int hh = (chunk << 5) + u;
        float gg[4];
        #pragma unroll
        for (int g = 0; g < 4; g++) {
            int j = (g << 9) + hh;
            float s = bih[j] + bhh[j];
            for (int sg = 0; sg < nseg; sg++)
                s += __ldcg(&g_part[((size_t)sg * 2048 + j) * Bc + b]);
            gg[g] = s;
        }
        float cold = g_c[layer][b * Hc + hh];
        float i_ = 1.f / (1.f + expf(-gg[0]));
        float f_ = 1.f / (1.f + expf(-gg[1]));
        float gv = tanhf(gg[2]);
        float o_ = 1.f / (1.f + expf(-gg[3]));
        float cn = f_ * cold + i_ * gv;
        float hn = o_ * tanhf(cn);
        g_c[layer][b * Hc + hh] = cn;
        g_h[layer][nx][b * Hc + hh] = hn;
        if (layer == 1) g_concat[(size_t)(t * Bc + b) * KC + hh] = hn;  // concat h1 section
    }
    if (tid == 0) g_cnt[chunk] = 0;   // self-reset for next launch
}

// ---------------- final vocab projection: C(2048,32000) = concat @ fc_W^T + b ----------------
// 128x128 tile, 8x8 per thread, K-tile 8.
__global__ __launch_bounds__(256) void k_gemm(const float* __restrict__ W,
                                              const float* __restrict__ bias,
                                              float* __restrict__ out) {
    __shared__ float As[8][132];
    __shared__ float Bs[8][132];
    int n0 = blockIdx.x * 128;
    int m0 = blockIdx.y * 128;
    int tid = threadIdx.x;
    int tx = tid & 15, ty = tid >> 4;
    int lr = tid >> 1;            // 0..127 row within tile
    int lh = (tid & 1) * 4;       // k offset 0 or 4

    const float* Aptr = g_concat + (size_t)(m0 + lr) * KC + lh;
    const float* Bptr = W + (size_t)(n0 + lr) * KC + lh;

    float acc[8][8] = {};

    for (int k = 0; k < KC; k += 8) {
        __syncthreads();
        float4 av = *(const float4*)(Aptr + k);
        float4 bv = *(const float4*)(Bptr + k);
        As[lh + 0][lr] = av.x; As[lh + 1][lr] = av.y; As[lh + 2][lr] = av.z; As[lh + 3][lr] = av.w;
        Bs[lh + 0][lr] = bv.x; Bs[lh + 1][lr] = bv.y; Bs[lh + 2][lr] = bv.z; Bs[lh + 3][lr] = bv.w;
        __syncthreads();
        #pragma unroll
        for (int kk = 0; kk < 8; kk++) {
            float4 a0 = *(const float4*)&As[kk][ty * 8];
            float4 a1 = *(const float4*)&As[kk][ty * 8 + 4];
            float4 b0 = *(const float4*)&Bs[kk][tx * 8];
            float4 b1 = *(const float4*)&Bs[kk][tx * 8 + 4];
            float a[8] = {a0.x, a0.y, a0.z, a0.w, a1.x, a1.y, a1.z, a1.w};
            float bb[8] = {b0.x, b0.y, b0.z, b0.w, b1.x, b1.y, b1.z, b1.w};
            #pragma unroll
            for (int i = 0; i < 8; i++)
                #pragma unroll
                for (int j = 0; j < 8; j++)
                    acc[i][j] += a[i] * bb[j];
        }
    }

    float bs[8];
    #pragma unroll
    for (int j = 0; j < 8; j++) bs[j] = bias[n0 + tx * 8 + j];

    #pragma unroll
    for (int i = 0; i < 8; i++) {
        int r = m0 + ty * 8 + i;          // r = t*32 + b
        int b = r & 31, t = r >> 5;
        float* dst = out + (size_t)b * Tc * Vc + (size_t)t * Vc + n0 + tx * 8;
        float4 v0 = make_float4(acc[i][0] + bs[0], acc[i][1] + bs[1], acc[i][2] + bs[2], acc[i][3] + bs[3]);
        float4 v1 = make_float4(acc[i][4] + bs[4], acc[i][5] + bs[5], acc[i][6] + bs[6], acc[i][7] + bs[7]);
        *(float4*)dst = v0;
        *((float4*)dst + 1) = v1;
    }
}

// ---------------- final state copy ----------------
__global__ void k_final(float* __restrict__ out, int fin) {
    int i = blockIdx.x * blockDim.x + threadIdx.x;
    if (i < Bc * Hc) {
        out[OFF_H + i] = g_h[0][fin][i];
        out[OFF_H + Bc * Hc + i] = g_h[1][fin][i];
        out[OFF_C + i] = g_c[0][i];
        out[OFF_C + Bc * Hc + i] = g_c[1][i];
    }
}

// ---------------- launch ----------------
extern "C" void kernel_launch(void* const* d_in, const int* in_sizes, int n_in,
                              void* d_out, int out_size) {
    // ---- robust input resolution by element counts (bool masks may or may not
    //      be marshalled into d_in; never trust fixed positions for them) ----
    int idx_emb = -1, idx_enc = -1, idx_h0 = -1;
    for (int i = 0; i < n_in; i++) {
        if (in_sizes[i] == 16384000) { idx_emb = i; break; }
    }
    for (int i = 0; i < n_in; i++) {
        if (in_sizes[i] == 1048576) { idx_enc = i; break; }   // first 1M input = enc_outs
    }
    for (int i = 0; i < n_in; i++) {
        if (in_sizes[i] == 32768) { idx_h0 = i; break; }      // h0 then c0 adjacent
    }
    const int*   tok  = (const int*)d_in[0];
    const float* enc  = (const float*)d_in[idx_enc];
    const float* h0   = (const float*)d_in[idx_h0];
    const float* c0   = (const float*)d_in[idx_h0 + 1];
    const float* emb  = (const float*)d_in[idx_emb];
    const float* Wih0 = (const float*)d_in[idx_emb + 1];
    const float* Whh0 = (const float*)d_in[idx_emb + 2];
    const float* bih0 = (const float*)d_in[idx_emb + 3];
    const float* bhh0 = (const float*)d_in[idx_emb + 4];
    const float* Wih1 = (const float*)d_in[idx_emb + 5];
    const float* Whh1 = (const float*)d_in[idx_emb + 6];
    const float* bih1 = (const float*)d_in[idx_emb + 7];
    const float* bhh1 = (const float*)d_in[idx_emb + 8];
    const float* fcW  = (const float*)d_in[idx_emb + 9];
    const float* fcb  = (const float*)d_in[idx_emb + 10];
    float* out = (float*)d_out;

    k_init<<<(Bc * Hc + 255) / 256, 256>>>(h0, c0);
    k_embed<<<Tc * Bc, 128>>>(tok, emb);

    for (int t = 0; t < Tc; t++) {
        int pr = t & 1, nx = pr ^ 1;
        k_attn<<<Bc, 256>>>(enc, t, pr, out);
        k_lstm<<<dim3(16, 12), 256>>>(Wih0, Whh0, bih0, bhh0, 0, t, pr, nx, 12);
        k_lstm<<<dim3(16, 8),  256>>>(Wih1, Whh1, bih1, bhh1, 1, t, pr, nx, 8);
    }

    k_gemm<<<dim3(Vc / 128, (Tc * Bc) / 128), 256>>>(fcW, fcb, out);
    // T is even -> final states ended up in pingpong buffer 0
    k_final<<<(Bc * Hc + 255) / 256, 256>>>(out, 0);
}

// round 10
// speedup vs baseline: 1.3428x; 1.3428x over previous
#include <cuda_runtime.h>
#include <cuda_bf16.h>
#include <math.h>
#include <stdint.h>
#include <stddef.h>

// Problem constants
#define Bc 32
#define Tc 64
#define Sc 64
#define Vc 32000
#define Ec 512
#define Hc 512
#define KC 1536   // concat width = 2H + E

// Output layout offsets (floats): outputs (B,T,V), h (2,B,H), c (2,B,H), attn (B,T,S)
#define OFF_H   ((size_t)Bc * Tc * Vc)
#define OFF_C   (OFF_H + (size_t)2 * Bc * Hc)
#define OFF_ATT (OFF_C + (size_t)2 * Bc * Hc)

// ---------------- device scratch (no allocations allowed) ----------------
__device__ float g_concat[(size_t)Tc * Bc * KC];   // [t][b][ h1 | ctx | emb ]  12.6 MB
__device__ float g_part[12 * 2048 * Bc];           // split-K partial gates      3 MB
__device__ float g_h[2][2][Bc * Hc];               // [layer][pingpong][b*H+h]
__device__ float g_c[2][Bc * Hc];                  // [layer][b*H+h]
__device__ int   g_cnt[16];                        // last-block counters (self-resetting)

// bf16 split operands for tensor-core vocab projection
__device__ __nv_bfloat16 g_Whi[(size_t)Vc * KC];   // 98.3 MB
__device__ __nv_bfloat16 g_Wlo[(size_t)Vc * KC];   // 98.3 MB
__device__ __nv_bfloat16 g_Ahi[(size_t)Tc * Bc * KC];
__device__ __nv_bfloat16 g_Alo[(size_t)Tc * Bc * KC];

// ---------------- init: copy h0/c0 into state buffers ----------------
__global__ void k_init(const float* __restrict__ h0, const float* __restrict__ c0) {
    int i = blockIdx.x * blockDim.x + threadIdx.x;
    if (i < Bc * Hc) {
        g_h[0][0][i] = h0[i];
        g_h[1][0][i] = h0[Bc * Hc + i];
        g_c[0][i] = c0[i];
        g_c[1][i] = c0[Bc * Hc + i];
    }
}

// ---------------- embedding gather into concat buffer ----------------
__global__ void k_embed(const int* __restrict__ tok, const float* __restrict__ emb) {
    int r = blockIdx.x;          // r = t*32 + b
    int t = r >> 5, b = r & 31;
    int tk = tok[b * Tc + t];
    const float4* src = (const float4*)(emb + (size_t)tk * Ec);
    float4* dst = (float4*)(g_concat + (size_t)r * KC + 2 * Hc);
    for (int i = threadIdx.x; i < Ec / 4; i += blockDim.x) dst[i] = src[i];
}

// ---------------- split-bf16 conversion kernels ----------------
__global__ void k_cvtW(const float* __restrict__ src) {
    size_t i = ((size_t)blockIdx.x * 256 + threadIdx.x) * 4;
    float4 v = *(const float4*)(src + i);
    __nv_bfloat16 h0 = __float2bfloat16(v.x), h1 = __float2bfloat16(v.y);
    __nv_bfloat16 h2 = __float2bfloat16(v.z), h3 = __float2bfloat16(v.w);
    __nv_bfloat16 l0 = __float2bfloat16(v.x - __bfloat162float(h0));
    __nv_bfloat16 l1 = __float2bfloat16(v.y - __bfloat162float(h1));
    __nv_bfloat16 l2 = __float2bfloat16(v.z - __bfloat162float(h2));
    __nv_bfloat16 l3 = __float2bfloat16(v.w - __bfloat162float(h3));
    *(__nv_bfloat162*)&g_Whi[i]     = __halves2bfloat162(h0, h1);
    *(__nv_bfloat162*)&g_Whi[i + 2] = __halves2bfloat162(h2, h3);
    *(__nv_bfloat162*)&g_Wlo[i]     = __halves2bfloat162(l0, l1);
    *(__nv_bfloat162*)&g_Wlo[i + 2] = __halves2bfloat162(l2, l3);
}

__global__ void k_cvtA() {
    size_t i = ((size_t)blockIdx.x * 256 + threadIdx.x) * 4;
    float4 v = *(const float4*)(g_concat + i);
    __nv_bfloat16 h0 = __float2bfloat16(v.x), h1 = __float2bfloat16(v.y);
    __nv_bfloat16 h2 = __float2bfloat16(v.z), h3 = __float2bfloat16(v.w);
    __nv_bfloat16 l0 = __float2bfloat16(v.x - __bfloat162float(h0));
    __nv_bfloat16 l1 = __float2bfloat16(v.y - __bfloat162float(h1));
    __nv_bfloat16 l2 = __float2bfloat16(v.z - __bfloat162float(h2));
    __nv_bfloat16 l3 = __float2bfloat16(v.w - __bfloat162float(h3));
    *(__nv_bfloat162*)&g_Ahi[i]     = __halves2bfloat162(h0, h1);
    *(__nv_bfloat162*)&g_Ahi[i + 2] = __halves2bfloat162(h2, h3);
    *(__nv_bfloat162*)&g_Alo[i]     = __halves2bfloat162(l0, l1);
    *(__nv_bfloat162*)&g_Alo[i + 2] = __halves2bfloat162(l2, l3);
}

// ---------------- attention for step t (reads h1 prev, writes ctx + attn) ----------------
__global__ __launch_bounds__(256) void k_attn(const float* __restrict__ enc, int t, int pr,
                                              float* __restrict__ out) {
    int b = blockIdx.x;
    int tid = threadIdx.x, w = tid >> 5, lane = tid & 31;
    const float* q = &g_h[1][pr][b * Hc];
    const float* encb = enc + (size_t)b * Sc * Hc;
    __shared__ float sc[Sc];
    __shared__ float sa[Sc];

    #pragma unroll
    for (int i = 0; i < 8; i++) {
        int s = w * 8 + i;
        const float* e = encb + (size_t)s * Hc;
        float acc = 0.f;
        for (int h = lane; h < Hc; h += 32) acc += q[h] * e[h];
        #pragma unroll
        for (int o = 16; o; o >>= 1) acc += __shfl_down_sync(0xffffffffu, acc, o);
        if (lane == 0) sc[s] = acc * 0.04419417382415922f;   // 1/sqrt(512)
    }
    __syncthreads();

    if (w == 0) {
        float v0 = sc[lane], v1 = sc[lane + 32];
        float m = fmaxf(v0, v1);
        #pragma unroll
        for (int o = 16; o; o >>= 1) m = fmaxf(m, __shfl_xor_sync(0xffffffffu, m, o));
        float e0 = expf(v0 - m), e1 = expf(v1 - m);
        float ssum = e0 + e1;
        #pragma unroll
        for (int o = 16; o; o >>= 1) ssum += __shfl_xor_sync(0xffffffffu, ssum, o);
        float inv = 1.f / ssum;
        sa[lane] = e0 * inv;
        sa[lane + 32] = e1 * inv;
    }
    __syncthreads();

    if (tid < Sc) out[OFF_ATT + (size_t)b * Tc * Sc + (size_t)t * Sc + tid] = sa[tid];

    float* crow = g_concat + ((size_t)(t * Bc + b) * KC + Hc);
    for (int h = tid; h < Hc; h += 256) {
        float acc = 0.f;
        #pragma unroll 8
        for (int s = 0; s < Sc; s++) acc += sa[s] * encb[(size_t)s * Hc + h];
        crow[h] = acc;
    }
}

// ---------------- fused LSTM layer: split-K GEMM + last-block gate update ----------------
__global__ __launch_bounds__(256) void k_lstm(const float* __restrict__ Wih,
                                              const float* __restrict__ Whh,
                                              const float* __restrict__ bih,
                                              const float* __restrict__ bhh,
                                              int layer, int t, int pr, int nx, int nseg) {
    int chunk = blockIdx.x, seg = blockIdx.y;
    int k0 = seg * 128;
    int tid = threadIdx.x, w = tid >> 5, lane = tid & 31;

    const float* xbase; int xstride;
    const float* wbase; int wstride;
    if (layer == 0) {
        if (k0 < 2 * Hc) {
            xbase = g_concat + (size_t)(t * Bc) * KC + (k0 < Hc ? 2 * Hc + k0 : k0);
            xstride = KC;
        } else {
            xbase = g_h[0][pr] + (k0 - 2 * Hc);
            xstride = Hc;
        }
        if (k0 < 2 * Hc) { wbase = Wih + k0; wstride = Ec + Hc; }
        else             { wbase = Whh + (k0 - 2 * Hc); wstride = Hc; }
    } else {
        if (k0 < Hc) { xbase = g_h[0][nx] + k0; xstride = Hc; }
        else         { xbase = g_h[1][pr] + (k0 - Hc); xstride = Hc; }
        if (k0 < Hc) { wbase = Wih + k0; wstride = Hc; }
        else         { wbase = Whh + (k0 - Hc); wstride = Hc; }
    }

    __shared__ float xs[128][33];
    __shared__ float wsT[32][129];
    __shared__ int slast;

    #pragma unroll
    for (int ib = 0; ib < 4; ib++) {
        int b = w * 4 + ib;
        const float* xr = xbase + (size_t)b * xstride;
        #pragma unroll
        for (int i = 0; i < 4; i++) {
            int k = lane + 32 * i;
            xs[k][b] = xr[k];
        }
    }

    float acc[4][4] = {};
    int bq = tid & 7;
    int jq = tid >> 3;

    for (int kt = 0; kt < 4; kt++) {
        __syncthreads();
        #pragma unroll
        for (int i = 0; i < 16; i++) {
            int jl = w * 16 + i;
            int j = ((jl >> 5) << 9) + (chunk << 5) + (jl & 31);
            wsT[lane][jl] = wbase[(size_t)j * wstride + kt * 32 + lane];
        }
        __syncthreads();
        #pragma unroll
        for (int kk = 0; kk < 32; kk++) {
            int kg = kt * 32 + kk;
            float xv0 = xs[kg][4 * bq + 0], xv1 = xs[kg][4 * bq + 1];
            float xv2 = xs[kg][4 * bq + 2], xv3 = xs[kg][4 * bq + 3];
            float wv0 = wsT[kk][4 * jq + 0], wv1 = wsT[kk][4 * jq + 1];
            float wv2 = wsT[kk][4 * jq + 2], wv3 = wsT[kk][4 * jq + 3];
            acc[0][0] += wv0 * xv0; acc[0][1] += wv0 * xv1; acc[0][2] += wv0 * xv2; acc[0][3] += wv0 * xv3;
            acc[1][0] += wv1 * xv0; acc[1][1] += wv1 * xv1; acc[1][2] += wv1 * xv2; acc[1][3] += wv1 * xv3;
            acc[2][0] += wv2 * xv0; acc[2][1] += wv2 * xv1; acc[2][2] += wv2 * xv2; acc[2][3] += wv2 * xv3;
            acc[3][0] += wv3 * xv0; acc[3][1] += wv3 * xv1; acc[3][2] += wv3 * xv2; acc[3][3] += wv3 * xv3;
        }
    }

    #pragma unroll
    for (int ji = 0; ji < 4; ji++) {
        int jl = 4 * jq + ji;
        int j = ((jl >> 5) << 9) + (chunk << 5) + (jl & 31);
        float4 v = make_float4(acc[ji][0], acc[ji][1], acc[ji][2], acc[ji][3]);
        *(float4*)&g_part[((size_t)seg * 2048 + j) * Bc + 4 * bq] = v;
    }
    __threadfence();
    __syncthreads();
    if (tid == 0) {
        int old = atomicAdd(&g_cnt[chunk], 1);
        slast = (old == nseg - 1) ? 1 : 0;
    }
    __syncthreads();
    if (!slast) return;
    __threadfence();

    for (int p = tid; p < 1024; p += 256) {
        int u = p >> 5;
        int b = p & 31;
        int hh = (chunk << 5) + u;
        float gg[4];
        #pragma unroll
        for (int g = 0; g < 4; g++) {
            int j = (g << 9) + hh;
            float s = bih[j] + bhh[j];
            for (int sg = 0; sg < nseg; sg++)
                s += __ldcg(&g_part[((size_t)sg * 2048 + j) * Bc + b]);
            gg[g] = s;
        }
        float cold = g_c[layer][b * Hc + hh];
        float i_ = 1.f / (1.f + expf(-gg[0]));
        float f_ = 1.f / (1.f + expf(-gg[1]));
        float gv = tanhf(gg[2]);
        float o_ = 1.f / (1.f + expf(-gg[3]));
        float cn = f_ * cold + i_ * gv;
        float hn = o_ * tanhf(cn);
        g_c[layer][b * Hc + hh] = cn;
        g_h[layer][nx][b * Hc + hh] = hn;
        if (layer == 1) g_concat[(size_t)(t * Bc + b) * KC + hh] = hn;
    }
    if (tid == 0) g_cnt[chunk] = 0;
}

// ---------------- tensor-core vocab projection: split-bf16, 3-product ----------------
__device__ __forceinline__ void mma_bf16(float c[4], const uint32_t a[4], const uint32_t b[2]) {
    asm volatile("mma.sync.aligned.m16n8k16.row.col.f32.bf16.bf16.f32 "
                 "{%0,%1,%2,%3}, {%4,%5,%6,%7}, {%8,%9}, {%0,%1,%2,%3};"
                 : "+f"(c[0]), "+f"(c[1]), "+f"(c[2]), "+f"(c[3])
                 : "r"(a[0]), "r"(a[1]), "r"(a[2]), "r"(a[3]), "r"(b[0]), "r"(b[1]));
}

// Block tile 64(m) x 128(n), K-stage 32. 8 warps: 2(m) x 4(n), warp tile 32x32.
__global__ __launch_bounds__(256) void k_mma(const float* __restrict__ bias,
                                             float* __restrict__ out) {
    __shared__ __nv_bfloat16 As[2][64 * 48];    // [hi/lo][m][k] stride 48
    __shared__ __nv_bfloat16 Bs[2][128 * 48];   // [hi/lo][n][k] stride 48
    int m0 = blockIdx.x * 64;
    int n0 = blockIdx.y * 128;
    int tid = threadIdx.x, lane = tid & 31, wid = tid >> 5;
    int wm = wid & 1, wn = wid >> 1;
    int g = lane >> 2, q2 = (lane & 3) * 2;

    float acc[2][4][4];
    #pragma unroll
    for (int i = 0; i < 2; i++)
        #pragma unroll
        for (int j = 0; j < 4; j++)
            #pragma unroll
            for (int q = 0; q < 4; q++) acc[i][j][q] = 0.f;

    int arow = tid >> 2, akc = (tid & 3) * 8;

    for (int kt = 0; kt < KC / 32; kt++) {
        int k0 = kt * 32;
        *(uint4*)&As[0][arow * 48 + akc] = *(const uint4*)&g_Ahi[(size_t)(m0 + arow) * KC + k0 + akc];
        *(uint4*)&As[1][arow * 48 + akc] = *(const uint4*)&g_Alo[(size_t)(m0 + arow) * KC + k0 + akc];
        #pragma unroll
        for (int i = 0; i < 2; i++) {
            int idx = i * 256 + tid;
            int n = idx >> 2, kc = (idx & 3) * 8;
            *(uint4*)&Bs[0][n * 48 + kc] = *(const uint4*)&g_Whi[(size_t)(n0 + n) * KC + k0 + kc];
            *(uint4*)&Bs[1][n * 48 + kc] = *(const uint4*)&g_Wlo[(size_t)(n0 + n) * KC + k0 + kc];
        }
        __syncthreads();

        #pragma unroll
        for (int ks = 0; ks < 32; ks += 16) {
            uint32_t ah[2][4], al[2][4], bh[4][2], bl[4][2];
            #pragma unroll
            for (int m2 = 0; m2 < 2; m2++) {
                int rm = wm * 32 + m2 * 16;
                ah[m2][0] = *(uint32_t*)&As[0][(rm + g) * 48 + ks + q2];
                ah[m2][1] = *(uint32_t*)&As[0][(rm + 8 + g) * 48 + ks + q2];
                ah[m2][2] = *(uint32_t*)&As[0][(rm + g) * 48 + ks + 8 + q2];
                ah[m2][3] = *(uint32_t*)&As[0][(rm + 8 + g) * 48 + ks + 8 + q2];
                al[m2][0] = *(uint32_t*)&As[1][(rm + g) * 48 + ks + q2];
                al[m2][1] = *(uint32_t*)&As[1][(rm + 8 + g) * 48 + ks + q2];
                al[m2][2] = *(uint32_t*)&As[1][(rm + g) * 48 + ks + 8 + q2];
                al[m2][3] = *(uint32_t*)&As[1][(rm + 8 + g) * 48 + ks + 8 + q2];
            }
            #pragma unroll
            for (int n4 = 0; n4 < 4; n4++) {
                int cn = wn * 32 + n4 * 8;
                bh[n4][0] = *(uint32_t*)&Bs[0][(cn + g) * 48 + ks + q2];
                bh[n4][1] = *(uint32_t*)&Bs[0][(cn + g) * 48 + ks + 8 + q2];
                bl[n4][0] = *(uint32_t*)&Bs[1][(cn + g) * 48 + ks + q2];
                bl[n4][1] = *(uint32_t*)&Bs[1][(cn + g) * 48 + ks + 8 + q2];
            }
            #pragma unroll
            for (int m2 = 0; m2 < 2; m2++)
                #pragma unroll
                for (int n4 = 0; n4 < 4; n4++) {
                    mma_bf16(acc[m2][n4], ah[m2], bh[n4]);
                    mma_bf16(acc[m2][n4], ah[m2], bl[n4]);
                    mma_bf16(acc[m2][n4], al[m2], bh[n4]);
                }
        }
        __syncthreads();
    }

    // epilogue: add bias, remap row r=t*32+b -> out[b][t][:]
    #pragma unroll
    for (int m2 = 0; m2 < 2; m2++)
        #pragma unroll
        for (int n4 = 0; n4 < 4; n4++) {
            int gm = m0 + wm * 32 + m2 * 16 + g;
            int gn = n0 + wn * 32 + n4 * 8 + q2;
            float bb0 = bias[gn], bb1 = bias[gn + 1];
            int t0 = gm >> 5, b0 = gm & 31;
            float2 v0 = make_float2(acc[m2][n4][0] + bb0, acc[m2][n4][1] + bb1);
            *(float2*)&out[(size_t)b0 * Tc * Vc + (size_t)t0 * Vc + gn] = v0;
            int gm8 = gm + 8;
            int t1 = gm8 >> 5, b1 = gm8 & 31;
            float2 v1 = make_float2(acc[m2][n4][2] + bb0, acc[m2][n4][3] + bb1);
            *(float2*)&out[(size_t)b1 * Tc * Vc + (size_t)t1 * Vc + gn] = v1;
        }
}

// ---------------- final state copy ----------------
__global__ void k_final(float* __restrict__ out, int fin) {
    int i = blockIdx.x * blockDim.x + threadIdx.x;
    if (i < Bc * Hc) {
        out[OFF_H + i] = g_h[0][fin][i];
        out[OFF_H + Bc * Hc + i] = g_h[1][fin][i];
        out[OFF_C + i] = g_c[0][i];
        out[OFF_C + Bc * Hc + i] = g_c[1][i];
    }
}

// ---------------- launch ----------------
extern "C" void kernel_launch(void* const* d_in, const int* in_sizes, int n_in,
                              void* d_out, int out_size) {
    int idx_emb = -1, idx_enc = -1, idx_h0 = -1;
    for (int i = 0; i < n_in; i++) {
        if (in_sizes[i] == 16384000) { idx_emb = i; break; }
    }
    for (int i = 0; i < n_in; i++) {
        if (in_sizes[i] == 1048576) { idx_enc = i; break; }
    }
    for (int i = 0; i < n_in; i++) {
        if (in_sizes[i] == 32768) { idx_h0 = i; break; }
    }
    const int*   tok  = (const int*)d_in[0];
    const float* enc  = (const float*)d_in[idx_enc];
    const float* h0   = (const float*)d_in[idx_h0];
    const float* c0   = (const float*)d_in[idx_h0 + 1];
    const float* emb  = (const float*)d_in[idx_emb];
    const float* Wih0 = (const float*)d_in[idx_emb + 1];
    const float* Whh0 = (const float*)d_in[idx_emb + 2];
    const float* bih0 = (const float*)d_in[idx_emb + 3];
    const float* bhh0 = (const float*)d_in[idx_emb + 4];
    const float* Wih1 = (const float*)d_in[idx_emb + 5];
    const float* Whh1 = (const float*)d_in[idx_emb + 6];
    const float* bih1 = (const float*)d_in[idx_emb + 7];
    const float* bhh1 = (const float*)d_in[idx_emb + 8];
    const float* fcW  = (const float*)d_in[idx_emb + 9];
    const float* fcb  = (const float*)d_in[idx_emb + 10];
    float* out = (float*)d_out;

    // weight split-bf16 conversion (independent of recurrence; 49.152M elems / 1024 per block)
    k_cvtW<<<48000, 256>>>(fcW);

    k_init<<<(Bc * Hc + 255) / 256, 256>>>(h0, c0);
    k_embed<<<Tc * Bc, 128>>>(tok, emb);

    for (int t = 0; t < Tc; t++) {
        int pr = t & 1, nx = pr ^ 1;
        k_attn<<<Bc, 256>>>(enc, t, pr, out);
        k_lstm<<<dim3(16, 12), 256>>>(Wih0, Whh0, bih0, bhh0, 0, t, pr, nx, 12);
        k_lstm<<<dim3(16, 8),  256>>>(Wih1, Whh1, bih1, bhh1, 1, t, pr, nx, 8);
    }

    // concat split-bf16 conversion (3.146M elems / 1024 per block)
    k_cvtA<<<3072, 256>>>();

    // tensor-core vocab projection: grid m-inner (32) x n (250) for B-tile L2 reuse
    k_mma<<<dim3(Tc * Bc / 64, Vc / 128), 256>>>(fcb, out);

    k_final<<<(Bc * Hc + 255) / 256, 256>>>(out, 0);
}

// round 11
// speedup vs baseline: 1.5271x; 1.1372x over previous
#include <cuda_runtime.h>
#include <cuda_bf16.h>
#include <math.h>
#include <stdint.h>
#include <stddef.h>

// Problem constants
#define Bc 32
#define Tc 64
#define Sc 64
#define Vc 32000
#define Ec 512
#define Hc 512
#define KC 1536   // concat width = 2H + E

#define GRID_P 128   // persistent CTAs (<=148 SMs -> all co-resident)

// Output layout offsets (floats): outputs (B,T,V), h (2,B,H), c (2,B,H), attn (B,T,S)
#define OFF_H   ((size_t)Bc * Tc * Vc)
#define OFF_C   (OFF_H + (size_t)2 * Bc * Hc)
#define OFF_ATT (OFF_C + (size_t)2 * Bc * Hc)

// ---------------- device scratch (no allocations allowed) ----------------
__device__ float g_concat[(size_t)Tc * Bc * KC];   // [t][b][ h1 | ctx | emb ]  12.6 MB
__device__ float g_part[12 * 2048 * Bc];           // split-K partial gates
__device__ float g_c[2][Bc * Hc];                  // [layer][b*H+h]

// transposed [k][b] state for coalesced x-tile loads in the persistent kernel
__device__ float g_embT[Tc][Ec * Bc];              // 4 MB
__device__ float g_ctxT[Hc * Bc];
__device__ float g_h0T[Hc * Bc];
__device__ float g_h1T[Hc * Bc];

// grid barrier state (sense-reversal; even barrier count per launch -> parity-safe)
__device__ int g_bar_cnt;
__device__ int g_bar_sense;

// bf16 split operands for tensor-core vocab projection
__device__ __nv_bfloat16 g_Whi[(size_t)Vc * KC];
__device__ __nv_bfloat16 g_Wlo[(size_t)Vc * KC];
__device__ __nv_bfloat16 g_Ahi[(size_t)Tc * Bc * KC];
__device__ __nv_bfloat16 g_Alo[(size_t)Tc * Bc * KC];

// ---------------- init: copy h0/c0 into state buffers (transposed h) ----------------
__global__ void k_init(const float* __restrict__ h0, const float* __restrict__ c0) {
    int i = blockIdx.x * blockDim.x + threadIdx.x;
    if (i < Bc * Hc) {
        int h = i & (Hc - 1), b = i >> 9;
        g_h0T[h * Bc + b] = h0[i];
        g_h1T[h * Bc + b] = h0[Bc * Hc + i];
        g_c[0][i] = c0[i];
        g_c[1][i] = c0[Bc * Hc + i];
    }
}

// ---------------- embedding gathers ----------------
__global__ void k_embed(const int* __restrict__ tok, const float* __restrict__ emb) {
    int r = blockIdx.x;          // r = t*32 + b
    int t = r >> 5, b = r & 31;
    int tk = tok[b * Tc + t];
    const float4* src = (const float4*)(emb + (size_t)tk * Ec);
    float4* dst = (float4*)(g_concat + (size_t)r * KC + 2 * Hc);
    for (int i = threadIdx.x; i < Ec / 4; i += blockDim.x) dst[i] = src[i];
}

__global__ void k_embed2(const int* __restrict__ tok, const float* __restrict__ emb) {
    int r = blockIdx.x;          // r = t*32 + b
    int t = r >> 5, b = r & 31;
    int tk = tok[b * Tc + t];
    const float* src = emb + (size_t)tk * Ec;
    for (int k = threadIdx.x; k < Ec; k += blockDim.x)
        g_embT[t][k * Bc + b] = src[k];
}

// ---------------- split-bf16 conversion kernels ----------------
__global__ void k_cvtW(const float* __restrict__ src) {
    size_t i = ((size_t)blockIdx.x * 256 + threadIdx.x) * 4;
    float4 v = *(const float4*)(src + i);
    __nv_bfloat16 h0 = __float2bfloat16(v.x), h1 = __float2bfloat16(v.y);
    __nv_bfloat16 h2 = __float2bfloat16(v.z), h3 = __float2bfloat16(v.w);
    __nv_bfloat16 l0 = __float2bfloat16(v.x - __bfloat162float(h0));
    __nv_bfloat16 l1 = __float2bfloat16(v.y - __bfloat162float(h1));
    __nv_bfloat16 l2 = __float2bfloat16(v.z - __bfloat162float(h2));
    __nv_bfloat16 l3 = __float2bfloat16(v.w - __bfloat162float(h3));
    *(__nv_bfloat162*)&g_Whi[i]     = __halves2bfloat162(h0, h1);
    *(__nv_bfloat162*)&g_Whi[i + 2] = __halves2bfloat162(h2, h3);
    *(__nv_bfloat162*)&g_Wlo[i]     = __halves2bfloat162(l0, l1);
    *(__nv_bfloat162*)&g_Wlo[i + 2] = __halves2bfloat162(l2, l3);
}

__global__ void k_cvtA() {
    size_t i = ((size_t)blockIdx.x * 256 + threadIdx.x) * 4;
    float4 v = *(const float4*)(g_concat + i);
    __nv_bfloat16 h0 = __float2bfloat16(v.x), h1 = __float2bfloat16(v.y);
    __nv_bfloat16 h2 = __float2bfloat16(v.z), h3 = __float2bfloat16(v.w);
    __nv_bfloat16 l0 = __float2bfloat16(v.x - __bfloat162float(h0));
    __nv_bfloat16 l1 = __float2bfloat16(v.y - __bfloat162float(h1));
    __nv_bfloat16 l2 = __float2bfloat16(v.z - __bfloat162float(h2));
    __nv_bfloat16 l3 = __float2bfloat16(v.w - __bfloat162float(h3));
    *(__nv_bfloat162*)&g_Ahi[i]     = __halves2bfloat162(h0, h1);
    *(__nv_bfloat162*)&g_Ahi[i + 2] = __halves2bfloat162(h2, h3);
    *(__nv_bfloat162*)&g_Alo[i]     = __halves2bfloat162(l0, l1);
    *(__nv_bfloat162*)&g_Alo[i + 2] = __halves2bfloat162(l2, l3);
}

// ---------------- grid barrier (sense reversal) ----------------
__device__ __forceinline__ void gbar(int& sense) {
    __syncthreads();
    if (threadIdx.x == 0) {
        __threadfence();                       // release
        int t = atomicAdd(&g_bar_cnt, 1);
        if (t == GRID_P - 1) {
            atomicExch(&g_bar_cnt, 0);
            __threadfence();
            atomicExch(&g_bar_sense, sense ^ 1);
        } else {
            while (atomicAdd(&g_bar_sense, 0) == sense) __nanosleep(64);
        }
        __threadfence();                       // acquire
    }
    __syncthreads();
    sense ^= 1;
}

// ---------------- persistent recurrence kernel ----------------
// 128 CTAs x 256 threads. Per step: P1 attn (32 CTAs) | P2 L0 partials (16x8 jobs)
// | P3 L0 gates | P4 L1 partials (16x8 jobs) | P5 L1 gates. 5 grid barriers/step.
// NOTE: all reads of cross-CTA mutable buffers use __ldcg (L1 is not coherent
// across SMs inside one launch). Weights are read-only -> cached in L1, and each
// CTA touches the SAME weight slice every step -> L1-resident across steps.
__global__ __launch_bounds__(256) void k_recur(
    const float* __restrict__ enc,
    const float* __restrict__ Wih0, const float* __restrict__ Whh0,
    const float* __restrict__ bih0, const float* __restrict__ bhh0,
    const float* __restrict__ Wih1, const float* __restrict__ Whh1,
    const float* __restrict__ bih1, const float* __restrict__ bhh1,
    float* __restrict__ out)
{
    __shared__ float xs[192 * 33];    // x tile [k][b] (layer0: 192 rows, layer1: 128)
    __shared__ float wsT[32 * 129];   // W sub-tile [k][j_local]; reused as q in P1
    __shared__ float sc[Sc];
    __shared__ float sa[Sc];

    const int bid = blockIdx.x;
    const int tid = threadIdx.x, w = tid >> 5, lane = tid & 31;
    const int bq = tid & 7;      // b-group (4 b each)
    const int jq = tid >> 3;     // j-group (4 j each, 0..31)
    const int chunk = bid & 15;  // 32 hidden units
    const int seg = bid >> 4;    // k-segment 0..7
    int sense = 0;

    for (int t = 0; t < Tc; t++) {
        // ---------- P1: attention (CTAs 0..31, b = bid) ----------
        if (bid < Bc) {
            int b = bid;
            float* qs = wsT;   // 512 floats
            for (int i = tid; i < Hc; i += 256) qs[i] = __ldcg(&g_h1T[i * Bc + b]);
            __syncthreads();
            const float* encb = enc + (size_t)b * Sc * Hc;
            #pragma unroll
            for (int i = 0; i < 8; i++) {
                int s = w * 8 + i;
                const float* e = encb + (size_t)s * Hc;
                float acc = 0.f;
                for (int h = lane; h < Hc; h += 32) acc += qs[h] * e[h];
                #pragma unroll
                for (int o = 16; o; o >>= 1) acc += __shfl_down_sync(0xffffffffu, acc, o);
                if (lane == 0) sc[s] = acc * 0.04419417382415922f;  // 1/sqrt(512)
            }
            __syncthreads();
            if (w == 0) {
                float v0 = sc[lane], v1 = sc[lane + 32];
                float m = fmaxf(v0, v1);
                #pragma unroll
                for (int o = 16; o; o >>= 1) m = fmaxf(m, __shfl_xor_sync(0xffffffffu, m, o));
                float e0 = expf(v0 - m), e1 = expf(v1 - m);
                float ssum = e0 + e1;
                #pragma unroll
                for (int o = 16; o; o >>= 1) ssum += __shfl_xor_sync(0xffffffffu, ssum, o);
                float inv = 1.f / ssum;
                sa[lane] = e0 * inv;
                sa[lane + 32] = e1 * inv;
            }
            __syncthreads();
            if (tid < Sc) out[OFF_ATT + (size_t)b * Tc * Sc + (size_t)t * Sc + tid] = sa[tid];
            for (int h = tid; h < Hc; h += 256) {
                float acc = 0.f;
                #pragma unroll 8
                for (int s = 0; s < Sc; s++) acc += sa[s] * encb[(size_t)s * Hc + h];
                g_ctxT[h * Bc + b] = acc;
                g_concat[((size_t)(t * Bc + b)) * KC + Hc + h] = acc;
            }
        }
        gbar(sense);

        // ---------- P2 / P4: split-K GEMM partials ----------
        #pragma unroll 1
        for (int layer = 0; layer < 2; layer++) {
            const int KSEG = (layer == 0) ? 192 : 128;
            const int k0 = seg * KSEG;
            // load x tile rows (coalesced: 32 consecutive b per k-row)
            for (int r = w; r < KSEG; r += 8) {
                int gk = k0 + r;
                const float* src;
                if (layer == 0) {
                    if (gk < Ec)            src = &g_embT[t][gk * Bc];
                    else if (gk < Ec + Hc)  src = &g_ctxT[(gk - Ec) * Bc];
                    else                    src = &g_h0T[(gk - Ec - Hc) * Bc];
                } else {
                    src = (gk < Hc) ? &g_h0T[gk * Bc] : &g_h1T[(gk - Hc) * Bc];
                }
                xs[r * 33 + lane] = __ldcg(&src[lane]);
            }

            float acc[4][4] = {};
            const float* Wih = layer ? Wih1 : Wih0;
            const float* Whh = layer ? Whh1 : Whh0;
            const int nkt = KSEG / 32;
            for (int kt = 0; kt < nkt; kt++) {
                __syncthreads();
                int gk = k0 + kt * 32;
                const float* wptr; int wstr;
                if (layer == 0) {
                    if (gk < Ec + Hc) { wptr = Wih + gk;            wstr = Ec + Hc; }
                    else              { wptr = Whh + (gk - Ec - Hc); wstr = Hc; }
                } else {
                    if (gk < Hc)      { wptr = Wih + gk;            wstr = Hc; }
                    else              { wptr = Whh + (gk - Hc);      wstr = Hc; }
                }
                #pragma unroll
                for (int i = 0; i < 16; i++) {
                    int jl = w * 16 + i;
                    int j = ((jl >> 5) << 9) + (chunk << 5) + (jl & 31);
                    wsT[lane * 129 + jl] = wptr[(size_t)j * wstr + lane];
                }
                __syncthreads();
                #pragma unroll
                for (int kk = 0; kk < 32; kk++) {
                    int kg = kt * 32 + kk;
                    float xv0 = xs[kg * 33 + 4 * bq + 0], xv1 = xs[kg * 33 + 4 * bq + 1];
                    float xv2 = xs[kg * 33 + 4 * bq + 2], xv3 = xs[kg * 33 + 4 * bq + 3];
                    float wv0 = wsT[kk * 129 + 4 * jq + 0], wv1 = wsT[kk * 129 + 4 * jq + 1];
                    float wv2 = wsT[kk * 129 + 4 * jq + 2], wv3 = wsT[kk * 129 + 4 * jq + 3];
                    acc[0][0] += wv0 * xv0; acc[0][1] += wv0 * xv1; acc[0][2] += wv0 * xv2; acc[0][3] += wv0 * xv3;
                    acc[1][0] += wv1 * xv0; acc[1][1] += wv1 * xv1; acc[1][2] += wv1 * xv2; acc[1][3] += wv1 * xv3;
                    acc[2][0] += wv2 * xv0; acc[2][1] += wv2 * xv1; acc[2][2] += wv2 * xv2; acc[2][3] += wv2 * xv3;
                    acc[3][0] += wv3 * xv0; acc[3][1] += wv3 * xv1; acc[3][2] += wv3 * xv2; acc[3][3] += wv3 * xv3;
                }
            }
            #pragma unroll
            for (int ji = 0; ji < 4; ji++) {
                int jl = 4 * jq + ji;
                int j = ((jl >> 5) << 9) + (chunk << 5) + (jl & 31);
                float4 v = make_float4(acc[ji][0], acc[ji][1], acc[ji][2], acc[ji][3]);
                *(float4*)&g_part[((size_t)seg * 2048 + j) * Bc + 4 * bq] = v;
            }
            __syncthreads();   // xs/wsT reuse safety before barrier
            gbar(sense);

            // ---------- P3 / P5: gate reduce + state update (128 cells/CTA) ----------
            if (tid < 128) {
                int cell = bid * 128 + tid;   // 16384 = 512h x 32b
                int h = cell >> 5, b = cell & 31;
                const float* bi = layer ? bih1 : bih0;
                const float* bh = layer ? bhh1 : bhh0;
                float gg[4];
                #pragma unroll
                for (int g = 0; g < 4; g++) {
                    int j = (g << 9) + h;
                    float s = bi[j] + bh[j];
                    #pragma unroll
                    for (int sg = 0; sg < 8; sg++)
                        s += __ldcg(&g_part[((size_t)sg * 2048 + j) * Bc + b]);
                    gg[g] = s;
                }
                float* cptr = &g_c[layer][b * Hc + h];
                float cold = *cptr;   // same CTA owns this cell every step
                float i_ = 1.f / (1.f + expf(-gg[0]));
                float f_ = 1.f / (1.f + expf(-gg[1]));
                float gv = tanhf(gg[2]);
                float o_ = 1.f / (1.f + expf(-gg[3]));
                float cn = f_ * cold + i_ * gv;
                float hn = o_ * tanhf(cn);
                *cptr = cn;
                if (layer == 0) {
                    g_h0T[h * Bc + b] = hn;
                } else {
                    g_h1T[h * Bc + b] = hn;
                    g_concat[((size_t)(t * Bc + b)) * KC + h] = hn;
                }
            }
            gbar(sense);
        }
    }
}

// ---------------- tensor-core vocab projection: split-bf16, 3-product ----------------
__device__ __forceinline__ void mma_bf16(float c[4], const uint32_t a[4], const uint32_t b[2]) {
    asm volatile("mma.sync.aligned.m16n8k16.row.col.f32.bf16.bf16.f32 "
                 "{%0,%1,%2,%3}, {%4,%5,%6,%7}, {%8,%9}, {%0,%1,%2,%3};"
                 : "+f"(c[0]), "+f"(c[1]), "+f"(c[2]), "+f"(c[3])
                 : "r"(a[0]), "r"(a[1]), "r"(a[2]), "r"(a[3]), "r"(b[0]), "r"(b[1]));
}

__global__ __launch_bounds__(256) void k_mma(const float* __restrict__ bias,
                                             float* __restrict__ out) {
    __shared__ __nv_bfloat16 As[2][64 * 48];
    __shared__ __nv_bfloat16 Bs[2][128 * 48];
    int m0 = blockIdx.x * 64;
    int n0 = blockIdx.y * 128;
    int tid = threadIdx.x, lane = tid & 31, wid = tid >> 5;
    int wm = wid & 1, wn = wid >> 1;
    int g = lane >> 2, q2 = (lane & 3) * 2;

    float acc[2][4][4];
    #pragma unroll
    for (int i = 0; i < 2; i++)
        #pragma unroll
        for (int j = 0; j < 4; j++)
            #pragma unroll
            for (int q = 0; q < 4; q++) acc[i][j][q] = 0.f;

    int arow = tid >> 2, akc = (tid & 3) * 8;

    for (int kt = 0; kt < KC / 32; kt++) {
        int k0 = kt * 32;
        *(uint4*)&As[0][arow * 48 + akc] = *(const uint4*)&g_Ahi[(size_t)(m0 + arow) * KC + k0 + akc];
        *(uint4*)&As[1][arow * 48 + akc] = *(const uint4*)&g_Alo[(size_t)(m0 + arow) * KC + k0 + akc];
        #pragma unroll
        for (int i = 0; i < 2; i++) {
            int idx = i * 256 + tid;
            int n = idx >> 2, kc = (idx & 3) * 8;
            *(uint4*)&Bs[0][n * 48 + kc] = *(const uint4*)&g_Whi[(size_t)(n0 + n) * KC + k0 + kc];
            *(uint4*)&Bs[1][n * 48 + kc] = *(const uint4*)&g_Wlo[(size_t)(n0 + n) * KC + k0 + kc];
        }
        __syncthreads();

        #pragma unroll
        for (int ks = 0; ks < 32; ks += 16) {
            uint32_t ah[2][4], al[2][4], bh[4][2], bl[4][2];
            #pragma unroll
            for (int m2 = 0; m2 < 2; m2++) {
                int rm = wm * 32 + m2 * 16;
                ah[m2][0] = *(uint32_t*)&As[0][(rm + g) * 48 + ks + q2];
                ah[m2][1] = *(uint32_t*)&As[0][(rm + 8 + g) * 48 + ks + q2];
                ah[m2][2] = *(uint32_t*)&As[0][(rm + g) * 48 + ks + 8 + q2];
                ah[m2][3] = *(uint32_t*)&As[0][(rm + 8 + g) * 48 + ks + 8 + q2];
                al[m2][0] = *(uint32_t*)&As[1][(rm + g) * 48 + ks + q2];
                al[m2][1] = *(uint32_t*)&As[1][(rm + 8 + g) * 48 + ks + q2];
                al[m2][2] = *(uint32_t*)&As[1][(rm + g) * 48 + ks + 8 + q2];
                al[m2][3] = *(uint32_t*)&As[1][(rm + 8 + g) * 48 + ks + 8 + q2];
            }
            #pragma unroll
            for (int n4 = 0; n4 < 4; n4++) {
                int cn = wn * 32 + n4 * 8;
                bh[n4][0] = *(uint32_t*)&Bs[0][(cn + g) * 48 + ks + q2];
                bh[n4][1] = *(uint32_t*)&Bs[0][(cn + g) * 48 + ks + 8 + q2];
                bl[n4][0] = *(uint32_t*)&Bs[1][(cn + g) * 48 + ks + q2];
                bl[n4][1] = *(uint32_t*)&Bs[1][(cn + g) * 48 + ks + 8 + q2];
            }
            #pragma unroll
            for (int m2 = 0; m2 < 2; m2++)
                #pragma unroll
                for (int n4 = 0; n4 < 4; n4++) {
                    mma_bf16(acc[m2][n4], ah[m2], bh[n4]);
                    mma_bf16(acc[m2][n4], ah[m2], bl[n4]);
                    mma_bf16(acc[m2][n4], al[m2], bh[n4]);
                }
        }
        __syncthreads();
    }

    #pragma unroll
    for (int m2 = 0; m2 < 2; m2++)
        #pragma unroll
        for (int n4 = 0; n4 < 4; n4++) {
            int gm = m0 + wm * 32 + m2 * 16 + g;
            int gn = n0 + wn * 32 + n4 * 8 + q2;
            float bb0 = bias[gn], bb1 = bias[gn + 1];
            int t0 = gm >> 5, b0 = gm & 31;
            float2 v0 = make_float2(acc[m2][n4][0] + bb0, acc[m2][n4][1] + bb1);
            *(float2*)&out[(size_t)b0 * Tc * Vc + (size_t)t0 * Vc + gn] = v0;
            int gm8 = gm + 8;
            int t1 = gm8 >> 5, b1 = gm8 & 31;
            float2 v1 = make_float2(acc[m2][n4][2] + bb0, acc[m2][n4][3] + bb1);
            *(float2*)&out[(size_t)b1 * Tc * Vc + (size_t)t1 * Vc + gn] = v1;
        }
}

// ---------------- final state copy (h transposed back) ----------------
__global__ void k_final(float* __restrict__ out) {
    int i = blockIdx.x * blockDim.x + threadIdx.x;
    if (i < Bc * Hc) {
        int h = i & (Hc - 1), b = i >> 9;
        out[OFF_H + i] = g_h0T[h * Bc + b];
        out[OFF_H + Bc * Hc + i] = g_h1T[h * Bc + b];
        out[OFF_C + i] = g_c[0][i];
        out[OFF_C + Bc * Hc + i] = g_c[1][i];
    }
}

// ---------------- launch ----------------
extern "C" void kernel_launch(void* const* d_in, const int* in_sizes, int n_in,
                              void* d_out, int out_size) {
    int idx_emb = -1, idx_enc = -1, idx_h0 = -1;
    for (int i = 0; i < n_in; i++) {
        if (in_sizes[i] == 16384000) { idx_emb = i; break; }
    }
    for (int i = 0; i < n_in; i++) {
        if (in_sizes[i] == 1048576) { idx_enc = i; break; }
    }
    for (int i = 0; i < n_in; i++) {
        if (in_sizes[i] == 32768) { idx_h0 = i; break; }
    }
    const int*   tok  = (const int*)d_in[0];
    const float* enc  = (const float*)d_in[idx_enc];
    const float* h0   = (const float*)d_in[idx_h0];
    const float* c0   = (const float*)d_in[idx_h0 + 1];
    const float* emb  = (const float*)d_in[idx_emb];
    const float* Wih0 = (const float*)d_in[idx_emb + 1];
    const float* Whh0 = (const float*)d_in[idx_emb + 2];
    const float* bih0 = (const float*)d_in[idx_emb + 3];
    const float* bhh0 = (const float*)d_in[idx_emb + 4];
    const float* Wih1 = (const float*)d_in[idx_emb + 5];
    const float* Whh1 = (const float*)d_in[idx_emb + 6];
    const float* bih1 = (const float*)d_in[idx_emb + 7];
    const float* bhh1 = (const float*)d_in[idx_emb + 8];
    const float* fcW  = (const float*)d_in[idx_emb + 9];
    const float* fcb  = (const float*)d_in[idx_emb + 10];
    float* out = (float*)d_out;

    k_cvtW<<<48000, 256>>>(fcW);

    k_init<<<(Bc * Hc + 255) / 256, 256>>>(h0, c0);
    k_embed<<<Tc * Bc, 128>>>(tok, emb);    // concat emb section (for cvtA)
    k_embed2<<<Tc * Bc, 128>>>(tok, emb);   // transposed emb (for recurrence)

    // whole recurrence in ONE persistent kernel (128 co-resident CTAs)
    k_recur<<<GRID_P, 256>>>(enc, Wih0, Whh0, bih0, bhh0,
                             Wih1, Whh1, bih1, bhh1, out);

    k_cvtA<<<3072, 256>>>();
    k_mma<<<dim3(Tc * Bc / 64, Vc / 128), 256>>>(fcb, out);
    k_final<<<(Bc * Hc + 255) / 256, 256>>>(out);
}